// round 16
// baseline (speedup 1.0000x reference)
#include <cuda_runtime.h>
#include <cuda_bf16.h>
#include <cuda_fp16.h>
#include <math.h>
#include <stdint.h>

#define BB 64
#define FF 256
#define TT 1024
#define HH 1024
#define OO 512
#define NB 128   // persistent CTAs: 4 batch-row groups x 32 H-col tiles

// Scratch (allocation-free rule: __device__ globals)
__device__ float  g_Z[(size_t)TT * BB * HH];    // Z = x@Wx + b, [t][b][h] (fp32, read by rec)
__device__ __half g_Sh[(size_t)TT * BB * HH];   // fp16 states row-major [t*64+b][h] (feeds out_kernel)
__device__ __half g_ST2h[2][4][HH * 16];        // fp16 transposed state ping-pong, [buf][r-group][h][16 b]
__device__ __half g_Wouth[HH * OO];             // fp16 Wout
__device__ __half g_Wxh[FF * HH];               // fp16 Wx
__device__ __half g_xh[(size_t)BB * FF * TT];   // fp16 x, [b][f][t]
__device__ unsigned g_flag[128 * 32];           // per-(cta, pair) generation flags: cta*32 + pair*8

// ---------------------------------------------------------------- helpers
__device__ __forceinline__ void cp_async16(void* smem_dst, const void* gmem_src) {
    unsigned s = (unsigned)__cvta_generic_to_shared(smem_dst);
    asm volatile("cp.async.cg.shared.global [%0], [%1], 16;\n" :: "r"(s), "l"(gmem_src));
}
__device__ __forceinline__ void cp_commit() { asm volatile("cp.async.commit_group;\n"); }
template <int N> __device__ __forceinline__ void cp_wait() {
    asm volatile("cp.async.wait_group %0;\n" :: "n"(N));
}

__device__ __forceinline__ void mbar_init(uint32_t mb, uint32_t count) {
    asm volatile("mbarrier.init.shared.b64 [%0], %1;" :: "r"(mb), "r"(count) : "memory");
}
__device__ __forceinline__ void mbar_expect_tx(uint32_t mb, uint32_t bytes) {
    asm volatile("mbarrier.arrive.expect_tx.shared.b64 _, [%0], %1;" :: "r"(mb), "r"(bytes) : "memory");
}
__device__ __forceinline__ void bulk_g2s(uint32_t dst_smem, const void* src, uint32_t bytes, uint32_t mb) {
    asm volatile("cp.async.bulk.shared::cluster.global.mbarrier::complete_tx::bytes [%0], [%1], %2, [%3];"
                 :: "r"(dst_smem), "l"(src), "r"(bytes), "r"(mb) : "memory");
}
__device__ __forceinline__ void mbar_wait(uint32_t mb, int ph) {
    asm volatile(
        "{\n\t"
        ".reg .pred P;\n\t"
        "W%=:\n\t"
        "mbarrier.try_wait.parity.acquire.cta.shared::cta.b64 P, [%0], %1, 0x989680;\n\t"
        "@P bra D%=;\n\t"
        "bra W%=;\n\t"
        "D%=:\n\t"
        "}" :: "r"(mb), "r"(ph) : "memory");
}

__device__ __forceinline__ unsigned ld_acq_gpu(const unsigned* p) {
    unsigned v;
    asm volatile("ld.acquire.gpu.global.u32 %0, [%1];" : "=r"(v) : "l"(p) : "memory");
    return v;
}
__device__ __forceinline__ void bar_named(int id, int cnt) {
    asm volatile("bar.sync %0, %1;" :: "r"(id), "r"(cnt) : "memory");
}

__device__ __forceinline__ void ldsm_x4(uint32_t& r0, uint32_t& r1, uint32_t& r2, uint32_t& r3, uint32_t addr) {
    asm volatile("ldmatrix.sync.aligned.m8n8.x4.shared.b16 {%0,%1,%2,%3}, [%4];"
                 : "=r"(r0), "=r"(r1), "=r"(r2), "=r"(r3) : "r"(addr));
}
__device__ __forceinline__ void ldsm_x4_trans(uint32_t& r0, uint32_t& r1, uint32_t& r2, uint32_t& r3, uint32_t addr) {
    asm volatile("ldmatrix.sync.aligned.m8n8.x4.trans.shared.b16 {%0,%1,%2,%3}, [%4];"
                 : "=r"(r0), "=r"(r1), "=r"(r2), "=r"(r3) : "r"(addr));
}
__device__ __forceinline__ void ldsm_x2_trans(uint32_t& r0, uint32_t& r1, uint32_t addr) {
    asm volatile("ldmatrix.sync.aligned.m8n8.x2.trans.shared.b16 {%0,%1}, [%2];"
                 : "=r"(r0), "=r"(r1) : "r"(addr));
}
__device__ __forceinline__ void mma16816(float& d0, float& d1, float& d2, float& d3,
                                         uint32_t a0, uint32_t a1, uint32_t a2, uint32_t a3,
                                         uint32_t b0, uint32_t b1) {
    asm volatile("mma.sync.aligned.m16n8k16.row.col.f32.f16.f16.f32 "
                 "{%0,%1,%2,%3}, {%4,%5,%6,%7}, {%8,%9}, {%0,%1,%2,%3};"
                 : "+f"(d0), "+f"(d1), "+f"(d2), "+f"(d3)
                 : "r"(a0), "r"(a1), "r"(a2), "r"(a3), "r"(b0), "r"(b1));
}

// ---------------------------------------------------------------- small prep kernels
__global__ void reset_kernel() {
    for (int i = threadIdx.x; i < 128 * 32; i += blockDim.x) g_flag[i] = 0u;
}
__global__ void wcvt_kernel(const float* __restrict__ Wout) {
    int i = blockIdx.x * 256 + threadIdx.x;
    g_Wouth[i] = __float2half_rn(Wout[i]);
}
__global__ void wxcvt_kernel(const float* __restrict__ Wx) {
    int i = blockIdx.x * 256 + threadIdx.x;
    g_Wxh[i] = __float2half_rn(Wx[i]);
}
__global__ void xcvt_kernel(const float* __restrict__ x) {
    size_t i = ((size_t)blockIdx.x * 256 + threadIdx.x) * 4;
    float4 v = *reinterpret_cast<const float4*>(x + i);
    __half2* p = reinterpret_cast<__half2*>(g_xh + i);
    p[0] = __floats2half2_rn(v.x, v.y);
    p[1] = __floats2half2_rn(v.z, v.w);
}

// ---------------------------------------------------------------- Kernel A: Z[t][b][h] = b[h] + sum_f x[b][f][t] * Wx[f][h]  (HMMA fp16)
__global__ void __launch_bounds__(256, 2) zmat_kernel(const float* __restrict__ bias) {
    extern __shared__ __half hsm[];
    __half* As = hsm;                 // [2][32][136]
    __half* Bs = hsm + 2 * 32 * 136;  // [2][32][136]
    int h0 = blockIdx.x * 128;
    int t0 = blockIdx.y * 128;
    int b  = blockIdx.z;
    int tid = threadIdx.x;
    int w = tid >> 5, lane = tid & 31;

    float d[8][2][4];
    #pragma unroll
    for (int mt = 0; mt < 8; mt++)
        #pragma unroll
        for (int nt = 0; nt < 2; nt++)
            #pragma unroll
            for (int j = 0; j < 4; j++) d[mt][nt][j] = 0.f;

    auto issue = [&](int ci, int buf) {
        int f0 = ci * 32;
        __half* Ad = As + buf * 4352;
        __half* Bd = Bs + buf * 4352;
        #pragma unroll
        for (int it = 0; it < 2; it++) {
            int idx = it * 256 + tid;
            int f = idx >> 4, sg = idx & 15;
            cp_async16(Ad + f * 136 + sg * 8, g_xh + ((size_t)b * FF + f0 + f) * TT + t0 + sg * 8);
            cp_async16(Bd + f * 136 + sg * 8, g_Wxh + (size_t)(f0 + f) * HH + h0 + sg * 8);
        }
        cp_commit();
    };

    int brow = ((lane >> 3) & 1) * 8 + (lane & 7);
    int arow = ((lane >> 4) & 1) * 8 + (lane & 7);
    int acol = ((lane >> 3) & 1) * 8;

    issue(0, 0);
    for (int ci = 0; ci < 8; ci++) {
        if (ci < 7) { issue(ci + 1, (ci + 1) & 1); cp_wait<1>(); }
        else cp_wait<0>();
        __syncthreads();
        uint32_t a_base = (uint32_t)__cvta_generic_to_shared(As + (ci & 1) * 4352);
        uint32_t b_base = (uint32_t)__cvta_generic_to_shared(Bs + (ci & 1) * 4352);
        #pragma unroll
        for (int kt = 0; kt < 2; kt++) {
            uint32_t Bf[2][2];
            #pragma unroll
            for (int nt = 0; nt < 2; nt++) {
                uint32_t baddr = b_base + (uint32_t)((kt * 16 + brow) * 136 + w * 16 + nt * 8) * 2;
                ldsm_x2_trans(Bf[nt][0], Bf[nt][1], baddr);
            }
            #pragma unroll
            for (int mt = 0; mt < 8; mt++) {
                uint32_t a0, a1, a2, a3;
                uint32_t aaddr = a_base + (uint32_t)((kt * 16 + arow) * 136 + mt * 16 + acol) * 2;
                ldsm_x4_trans(a0, a1, a2, a3, aaddr);
                mma16816(d[mt][0][0], d[mt][0][1], d[mt][0][2], d[mt][0][3],
                         a0, a1, a2, a3, Bf[0][0], Bf[0][1]);
                mma16816(d[mt][1][0], d[mt][1][1], d[mt][1][2], d[mt][1][3],
                         a0, a1, a2, a3, Bf[1][0], Bf[1][1]);
            }
        }
        __syncthreads();
    }

    int nc = (lane & 3) * 2;
    int mrow = lane >> 2;
    #pragma unroll
    for (int nt = 0; nt < 2; nt++) {
        int col = h0 + w * 16 + nt * 8 + nc;
        float2 bv = *reinterpret_cast<const float2*>(bias + col);
        #pragma unroll
        for (int mt = 0; mt < 8; mt++) {
            int ta = t0 + mt * 16 + mrow;
            int tb = ta + 8;
            *reinterpret_cast<float2*>(g_Z + ((size_t)ta * BB + b) * HH + col) =
                make_float2(d[mt][nt][0] + bv.x, d[mt][nt][1] + bv.y);
            *reinterpret_cast<float2*>(g_Z + ((size_t)tb * BB + b) * HH + col) =
                make_float2(d[mt][nt][2] + bv.x, d[mt][nt][3] + bv.y);
        }
    }
}

// ---------------------------------------------------------------- Kernel B: persistent recurrence — pair-split HMMA dataflow
// 128 CTAs: (r: 16 batch rows) x (c: 32 H cols). 256 threads = 8 warps = 4 pairs.
// Pair p owns n-cols [8p,8p+8); warp w: kh=w&1 computes K-half [512kh, 512kh+512).
// No block barriers in the t-loop: pair-local reduction (named barrier, parity-buffered),
// pair-local transposed store + per-pair flags. State SMEM double-buffered; warp w also
// self-stages chunk w (128 k) with its own mbarrier, polling 16 producer pair-flags.
__global__ void __launch_bounds__(256, 1) rnn_rec_kernel(const float* __restrict__ Wh) {
    extern __shared__ float smem[];
    // [0..16 floats): 8 full-mbarriers (one per chunk/warp)
    __half* wh_h = reinterpret_cast<__half*>(smem + 16);         // [1024][32] halfs (64KB)
    __half* st_h = reinterpret_cast<__half*>(smem + 16 + 16384); // [2][1024][16] halfs (64KB)
    float*  red_s = smem + 16 + 16384 + 16384;                   // [4 pairs][2 buf][128] floats (4KB)
    __half* finh = reinterpret_cast<__half*>(red_s + 1024);      // [4 pairs][16][12] halfs
    uint32_t mbar0 = (uint32_t)__cvta_generic_to_shared(smem);
    uint32_t st_base = (uint32_t)__cvta_generic_to_shared(st_h);
    uint32_t wh_base = (uint32_t)__cvta_generic_to_shared(wh_h);

    int tid  = threadIdx.x;
    int wid  = tid >> 5, lane = tid & 31;
    int c = blockIdx.x & 31;                // column tile (32 cols)
    int r = blockIdx.x >> 5;                // batch row group (16 rows)
    int r16 = r * 16;

    if (tid == 0) {
        #pragma unroll
        for (int w2 = 0; w2 < 8; w2++) mbar_init(mbar0 + w2 * 8, 1);
    }
    for (int i = tid; i < 32768; i += 256) {
        int k = i >> 5, n = i & 31;
        wh_h[i] = __float2half_rn(Wh[k * HH + c * 32 + n]);
    }
    __syncthreads();

    int w = wid;
    int p = w >> 1;                         // pair
    int kh = w & 1;                         // K-half
    uint32_t mymb = mbar0 + w * 8;

    // Preload B fragments for this warp's K-half and pair n-tile: 32 k-tiles x 2 regs.
    uint32_t Bf[32][2];
    {
        int brow = ((lane >> 3) & 1) * 8 + (lane & 7);
        #pragma unroll
        for (int kt = 0; kt < 32; kt++) {
            int krow = kh * 512 + kt * 16 + brow;
            uint32_t addr = wh_base + (uint32_t)(krow * 32 + p * 8) * 2;
            ldsm_x2_trans(Bf[kt][0], Bf[kt][1], addr);
        }
    }

    // A ldmatrix (x4.trans from [k][16b]) address pattern
    int arow = ((lane >> 4) & 1) * 8 + (lane & 7);
    int acol = ((lane >> 3) & 1) * 8;

    // stager poll set: chunk w covers h [128w,128w+128) = CTAs 4w..4w+3, pairs 0..3
    const unsigned* pf = &g_flag[((r * 32 + 4 * w + (lane >> 2)) * 32) + (lane & 3) * 8];

    // D-frag / output mapping
    int m0 = lane >> 2;                     // 0..7
    int nc = (lane & 3) * 2;                // 0,2,4,6
    int hloc = p * 8 + nc;                  // local col of d0/d1
    int hcolg = c * 32 + hloc;              // global h
    // transposed-store mapping (kh0, lanes 0-15)
    int cc = lane >> 1;                     // 0..7 (col within pair tile)
    int bh = (lane & 1) * 8;                // 0 or 8 (b-half)
    __half* finp = finh + p * 192;          // [16][12]
    unsigned* myflag = &g_flag[(r * 32 + c) * 32 + p * 8];

    for (int t = 0; t < TT; ++t) {
        // prefetch Z terms (kh0 only needs them)
        float2 zq0, zq1;
        if (kh == 0) {
            const float* zb = g_Z + (size_t)t * (BB * HH);
            zq0 = *reinterpret_cast<const float2*>(zb + (size_t)(r16 + m0) * HH + hcolg);
            zq1 = *reinterpret_cast<const float2*>(zb + (size_t)(r16 + m0 + 8) * HH + hcolg);
        }

        float dA[4] = {0.f, 0.f, 0.f, 0.f};
        float dB[4] = {0.f, 0.f, 0.f, 0.f};

        if (t > 0) {
            // self-stage chunk w for this step
            if (lane < 16) {
                while (ld_acq_gpu(pf) < (unsigned)t) { }
            }
            __syncwarp();
            if (lane == 0) {
                asm volatile("fence.proxy.async;" ::: "memory");
                const __half* src = g_ST2h[(t + 1) & 1][r] + w * 2048;   // 2048 halfs = 4KB
                mbar_expect_tx(mymb, 4096u);
                uint32_t dst = st_base + (uint32_t)((t & 1) * 32768 + w * 4096);
                bulk_g2s(dst, src, 4096u, mymb);
            }
            // compute this warp's K-half over its 4 chunks as they arrive
            uint32_t stb = st_base + (uint32_t)((t & 1) * 32768);
            #pragma unroll
            for (int cch = 0; cch < 4; cch++) {
                int ch = kh * 4 + cch;
                mbar_wait(mbar0 + ch * 8, (t - 1) & 1);
                #pragma unroll
                for (int kt2 = 0; kt2 < 8; kt2++) {
                    int ktl = cch * 8 + kt2;
                    uint32_t a0, a1, a2, a3;
                    uint32_t addr = stb + (uint32_t)((ch * 128 + kt2 * 16 + arow) * 16 + acol) * 2;
                    ldsm_x4_trans(a0, a1, a2, a3, addr);
                    if (kt2 & 1)
                        mma16816(dB[0], dB[1], dB[2], dB[3], a0, a1, a2, a3, Bf[ktl][0], Bf[ktl][1]);
                    else
                        mma16816(dA[0], dA[1], dA[2], dA[3], a0, a1, a2, a3, Bf[ktl][0], Bf[ktl][1]);
                }
            }
        }
        float d0 = dA[0] + dB[0], d1 = dA[1] + dB[1];
        float d2 = dA[2] + dB[2], d3 = dA[3] + dB[3];

        // pair reduction: kh1 publishes partials (parity-buffered), kh0 sums
        float* rp = red_s + (p * 2 + (t & 1)) * 128;
        if (kh == 1) {
            *reinterpret_cast<float2*>(rp + m0 * 8 + nc)       = make_float2(d0, d1);
            *reinterpret_cast<float2*>(rp + (m0 + 8) * 8 + nc) = make_float2(d2, d3);
        }
        bar_named(1 + p, 64);
        if (kh == 0) {
            float2 p0 = *reinterpret_cast<const float2*>(rp + m0 * 8 + nc);
            float2 p1 = *reinterpret_cast<const float2*>(rp + (m0 + 8) * 8 + nc);
            float s0 = tanhf(zq0.x + d0 + p0.x);
            float s1 = tanhf(zq0.y + d1 + p0.y);
            float s2 = tanhf(zq1.x + d2 + p1.x);
            float s3 = tanhf(zq1.y + d3 + p1.y);
            // stage finals for transposed store (pair-local, conflict-free)
            *reinterpret_cast<__half2*>(finp + m0 * 12 + nc)       = __floats2half2_rn(s0, s1);
            *reinterpret_cast<__half2*>(finp + (m0 + 8) * 12 + nc) = __floats2half2_rn(s2, s3);
            __syncwarp();
            if (lane < 16) {
                // transposed fp16 state store: col cc, b-rows bh..bh+7 (16B)
                __half2 q0 = __halves2half2(finp[(bh + 0) * 12 + cc], finp[(bh + 1) * 12 + cc]);
                __half2 q1 = __halves2half2(finp[(bh + 2) * 12 + cc], finp[(bh + 3) * 12 + cc]);
                __half2 q2 = __halves2half2(finp[(bh + 4) * 12 + cc], finp[(bh + 5) * 12 + cc]);
                __half2 q3 = __halves2half2(finp[(bh + 6) * 12 + cc], finp[(bh + 7) * 12 + cc]);
                uint4 u = make_uint4(*reinterpret_cast<uint32_t*>(&q0), *reinterpret_cast<uint32_t*>(&q1),
                                     *reinterpret_cast<uint32_t*>(&q2), *reinterpret_cast<uint32_t*>(&q3));
                *reinterpret_cast<uint4*>(g_ST2h[t & 1][r] + (size_t)(c * 32 + p * 8 + cc) * 16 + bh) = u;
            }
            __syncwarp();
            if (lane == 0) {
                asm volatile("fence.acq_rel.gpu;" ::: "memory");
                unsigned g = (unsigned)(t + 1);
                asm volatile("st.relaxed.gpu.global.u32 [%0], %1;" :: "l"(myflag), "r"(g) : "memory");
            }
            // fp16 row-major states for out_kernel (off inter-CTA critical path)
            __half* shb = g_Sh + ((size_t)t * BB) * HH;
            *reinterpret_cast<__half2*>(shb + (size_t)(r16 + m0) * HH + hcolg)     = __floats2half2_rn(s0, s1);
            *reinterpret_cast<__half2*>(shb + (size_t)(r16 + m0 + 8) * HH + hcolg) = __floats2half2_rn(s2, s3);
        }
    }
}

// ---------------------------------------------------------------- Kernel C: out = S(fp16) @ Wout(fp16) + bout, HMMA
__global__ void __launch_bounds__(256, 2) out_kernel(const float* __restrict__ bout,
                                                     float* __restrict__ out) {
    extern __shared__ __half hsm[];
    __half* As = hsm;                 // [2][128][40]
    __half* Bs = hsm + 2 * 128 * 40;  // [2][32][136]
    int o0 = blockIdx.x * 128;
    int r0 = blockIdx.y * 128;
    int tid = threadIdx.x;
    int w = tid >> 5, lane = tid & 31;

    float d[8][2][4];
    #pragma unroll
    for (int mt = 0; mt < 8; mt++)
        #pragma unroll
        for (int nt = 0; nt < 2; nt++)
            #pragma unroll
            for (int j = 0; j < 4; j++) d[mt][nt][j] = 0.f;

    auto issue = [&](int ci, int buf) {
        int f0 = ci * 32;
        __half* Ad = As + buf * 5120;
        __half* Bd = Bs + buf * 4352;
        #pragma unroll
        for (int it = 0; it < 2; it++) {
            int idx = it * 256 + tid;
            int row = idx >> 2, seg = idx & 3;
            cp_async16(Ad + row * 40 + seg * 8, g_Sh + (size_t)(r0 + row) * HH + f0 + seg * 8);
            int kr = idx >> 4, sg = idx & 15;
            cp_async16(Bd + kr * 136 + sg * 8, g_Wouth + (size_t)(f0 + kr) * OO + o0 + sg * 8);
        }
        cp_commit();
    };

    int brow = ((lane >> 3) & 1) * 8 + (lane & 7);
    int amr = lane & 15;
    int akc = (lane >> 4) * 8;

    issue(0, 0);
    for (int ci = 0; ci < 32; ci++) {
        if (ci < 31) { issue(ci + 1, (ci + 1) & 1); cp_wait<1>(); }
        else cp_wait<0>();
        __syncthreads();
        const __half* Ac = As + (ci & 1) * 5120;
        const __half* Bc = Bs + (ci & 1) * 4352;
        uint32_t a_base = (uint32_t)__cvta_generic_to_shared(Ac);
        uint32_t b_base = (uint32_t)__cvta_generic_to_shared(Bc);
        #pragma unroll
        for (int kt = 0; kt < 2; kt++) {
            uint32_t Bf[2][2];
            #pragma unroll
            for (int nt = 0; nt < 2; nt++) {
                uint32_t baddr = b_base + (uint32_t)((kt * 16 + brow) * 136 + w * 16 + nt * 8) * 2;
                ldsm_x2_trans(Bf[nt][0], Bf[nt][1], baddr);
            }
            #pragma unroll
            for (int mt = 0; mt < 8; mt++) {
                uint32_t a0, a1, a2, a3;
                uint32_t aaddr = a_base + (uint32_t)((mt * 16 + amr) * 40 + kt * 16 + akc) * 2;
                ldsm_x4(a0, a1, a2, a3, aaddr);
                mma16816(d[mt][0][0], d[mt][0][1], d[mt][0][2], d[mt][0][3],
                         a0, a1, a2, a3, Bf[0][0], Bf[0][1]);
                mma16816(d[mt][1][0], d[mt][1][1], d[mt][1][2], d[mt][1][3],
                         a0, a1, a2, a3, Bf[1][0], Bf[1][1]);
            }
        }
        __syncthreads();
    }

    int nc = (lane & 3) * 2;
    int mrow = lane >> 2;
    #pragma unroll
    for (int nt = 0; nt < 2; nt++) {
        int col = o0 + w * 16 + nt * 8 + nc;
        float2 bv = *reinterpret_cast<const float2*>(bout + col);
        #pragma unroll
        for (int mt = 0; mt < 8; mt++) {
            int g0 = r0 + mt * 16 + mrow;
            int g1 = g0 + 8;
            int t0r = g0 >> 6, b0r = g0 & 63;
            int t1r = g1 >> 6, b1r = g1 & 63;
            *reinterpret_cast<float2*>(out + (size_t)b0r * (TT * OO) + t0r * OO + col) =
                make_float2(d[mt][nt][0] + bv.x, d[mt][nt][1] + bv.y);
            *reinterpret_cast<float2*>(out + (size_t)b1r * (TT * OO) + t1r * OO + col) =
                make_float2(d[mt][nt][2] + bv.x, d[mt][nt][3] + bv.y);
        }
    }
}

// ---------------------------------------------------------------- launch
extern "C" void kernel_launch(void* const* d_in, const int* in_sizes, int n_in,
                              void* d_out, int out_size) {
    const float* x    = (const float*)d_in[0];   // (B,F,T)
    const float* Wx   = (const float*)d_in[1];   // (F,H)
    const float* Wh   = (const float*)d_in[2];   // (H,H)
    const float* bv   = (const float*)d_in[3];   // (H,)
    const float* Wout = (const float*)d_in[4];   // (H,O)
    const float* bo   = (const float*)d_in[5];   // (O,)
    float* out = (float*)d_out;                  // (B,T,O)

    (void)in_sizes; (void)n_in; (void)out_size;

    // Phase 0: reset flags + fp16 conversions (x, Wx, Wout)
    reset_kernel<<<1, 256>>>();
    wcvt_kernel<<<(HH * OO) / 256, 256>>>(Wout);
    wxcvt_kernel<<<(FF * HH) / 256, 256>>>(Wx);
    xcvt_kernel<<<(int)(((size_t)BB * FF * TT) / 1024), 256>>>(x);

    // Phase 1: Z = x@Wx + b (HMMA fp16, 128x128 tiles, 2 CTAs/SM)
    size_t zsm = (size_t)(2 * 32 * 136 * 2) * sizeof(__half);   // 34816 B
    cudaFuncSetAttribute(zmat_kernel, cudaFuncAttributeMaxDynamicSharedMemorySize, (int)zsm);
    dim3 ga(HH / 128, TT / 128, BB);
    zmat_kernel<<<ga, 256, zsm>>>(bv);

    // Phase 2: persistent recurrence (pair-split HMMA dataflow, 256 threads)
    size_t dyn = (size_t)(16 + 16384 + 16384 + 1024) * sizeof(float) + 4 * 192 * sizeof(__half);  // ~136.6KB
    cudaFuncSetAttribute(rnn_rec_kernel, cudaFuncAttributeMaxDynamicSharedMemorySize, 232448);
    rnn_rec_kernel<<<NB, 256, dyn>>>(Wh);

    // Phase 3: output projection (HMMA fp16, 128x128 tiles, 2 CTAs/SM)
    size_t osm = (2 * 128 * 40 + 2 * 32 * 136) * sizeof(__half);  // 37888 B
    cudaFuncSetAttribute(out_kernel, cudaFuncAttributeMaxDynamicSharedMemorySize, (int)osm);
    dim3 gc(OO / 128, (TT * BB) / 128);   // n-inner for A-tile L2 reuse
    out_kernel<<<gc, 256, osm>>>(bo, out);
}

// round 17
// speedup vs baseline: 1.2836x; 1.2836x over previous
#include <cuda_runtime.h>
#include <cuda_bf16.h>
#include <cuda_fp16.h>
#include <math.h>
#include <stdint.h>

#define BB 64
#define FF 256
#define TT 1024
#define HH 1024
#define OO 512
#define NB 128   // persistent CTAs: 4 batch-row groups x 32 H-col tiles

// Scratch (allocation-free rule: __device__ globals)
__device__ float  g_Z[(size_t)TT * BB * HH];    // Z = x@Wx + b, [t][b][h] (fp32, read by rec)
__device__ __half g_Sh[(size_t)TT * BB * HH];   // fp16 states row-major [t*64+b][h] (feeds out_kernel)
__device__ __half g_ST2h[2][4][HH * 16];        // fp16 transposed state ping-pong, [buf][r-group][h][16 b]
__device__ __half g_Wouth[HH * OO];             // fp16 Wout
__device__ __half g_Wxh[FF * HH];               // fp16 Wx
__device__ __half g_xh[(size_t)BB * FF * TT];   // fp16 x, [b][f][t]
__device__ unsigned g_flag[4 * 32 * 32];        // per-(r,c) generation flags, 128B apart

// ---------------------------------------------------------------- helpers
__device__ __forceinline__ void cp_async16(void* smem_dst, const void* gmem_src) {
    unsigned s = (unsigned)__cvta_generic_to_shared(smem_dst);
    asm volatile("cp.async.cg.shared.global [%0], [%1], 16;\n" :: "r"(s), "l"(gmem_src));
}
__device__ __forceinline__ void cp_commit() { asm volatile("cp.async.commit_group;\n"); }
template <int N> __device__ __forceinline__ void cp_wait() {
    asm volatile("cp.async.wait_group %0;\n" :: "n"(N));
}

__device__ __forceinline__ void mbar_init(uint32_t mb, uint32_t count) {
    asm volatile("mbarrier.init.shared.b64 [%0], %1;" :: "r"(mb), "r"(count) : "memory");
}
__device__ __forceinline__ void mbar_expect_tx(uint32_t mb, uint32_t bytes) {
    asm volatile("mbarrier.arrive.expect_tx.shared.b64 _, [%0], %1;" :: "r"(mb), "r"(bytes) : "memory");
}
__device__ __forceinline__ void bulk_g2s(uint32_t dst_smem, const void* src, uint32_t bytes, uint32_t mb) {
    asm volatile("cp.async.bulk.shared::cluster.global.mbarrier::complete_tx::bytes [%0], [%1], %2, [%3];"
                 :: "r"(dst_smem), "l"(src), "r"(bytes), "r"(mb) : "memory");
}
__device__ __forceinline__ void mbar_wait(uint32_t mb, int ph) {
    asm volatile(
        "{\n\t"
        ".reg .pred P;\n\t"
        "W%=:\n\t"
        "mbarrier.try_wait.parity.acquire.cta.shared::cta.b64 P, [%0], %1, 0x989680;\n\t"
        "@P bra D%=;\n\t"
        "bra W%=;\n\t"
        "D%=:\n\t"
        "}" :: "r"(mb), "r"(ph) : "memory");
}

__device__ __forceinline__ unsigned ld_acq_gpu(const unsigned* p) {
    unsigned v;
    asm volatile("ld.acquire.gpu.global.u32 %0, [%1];" : "=r"(v) : "l"(p) : "memory");
    return v;
}
__device__ __forceinline__ void bar_named(int id, int cnt) {
    asm volatile("bar.sync %0, %1;" :: "r"(id), "r"(cnt) : "memory");
}

__device__ __forceinline__ void ldsm_x4(uint32_t& r0, uint32_t& r1, uint32_t& r2, uint32_t& r3, uint32_t addr) {
    asm volatile("ldmatrix.sync.aligned.m8n8.x4.shared.b16 {%0,%1,%2,%3}, [%4];"
                 : "=r"(r0), "=r"(r1), "=r"(r2), "=r"(r3) : "r"(addr));
}
__device__ __forceinline__ void ldsm_x4_trans(uint32_t& r0, uint32_t& r1, uint32_t& r2, uint32_t& r3, uint32_t addr) {
    asm volatile("ldmatrix.sync.aligned.m8n8.x4.trans.shared.b16 {%0,%1,%2,%3}, [%4];"
                 : "=r"(r0), "=r"(r1), "=r"(r2), "=r"(r3) : "r"(addr));
}
__device__ __forceinline__ void ldsm_x2_trans(uint32_t& r0, uint32_t& r1, uint32_t addr) {
    asm volatile("ldmatrix.sync.aligned.m8n8.x2.trans.shared.b16 {%0,%1}, [%2];"
                 : "=r"(r0), "=r"(r1) : "r"(addr));
}
__device__ __forceinline__ void mma16816(float& d0, float& d1, float& d2, float& d3,
                                         uint32_t a0, uint32_t a1, uint32_t a2, uint32_t a3,
                                         uint32_t b0, uint32_t b1) {
    asm volatile("mma.sync.aligned.m16n8k16.row.col.f32.f16.f16.f32 "
                 "{%0,%1,%2,%3}, {%4,%5,%6,%7}, {%8,%9}, {%0,%1,%2,%3};"
                 : "+f"(d0), "+f"(d1), "+f"(d2), "+f"(d3)
                 : "r"(a0), "r"(a1), "r"(a2), "r"(a3), "r"(b0), "r"(b1));
}

// ---------------------------------------------------------------- small prep kernels
__global__ void reset_kernel() {
    for (int i = threadIdx.x; i < 4 * 32 * 32; i += blockDim.x) g_flag[i] = 0u;
}
__global__ void wcvt_kernel(const float* __restrict__ Wout) {
    int i = blockIdx.x * 256 + threadIdx.x;
    g_Wouth[i] = __float2half_rn(Wout[i]);
}
__global__ void wxcvt_kernel(const float* __restrict__ Wx) {
    int i = blockIdx.x * 256 + threadIdx.x;
    g_Wxh[i] = __float2half_rn(Wx[i]);
}
__global__ void xcvt_kernel(const float* __restrict__ x) {
    size_t i = ((size_t)blockIdx.x * 256 + threadIdx.x) * 4;
    float4 v = *reinterpret_cast<const float4*>(x + i);
    __half2* p = reinterpret_cast<__half2*>(g_xh + i);
    p[0] = __floats2half2_rn(v.x, v.y);
    p[1] = __floats2half2_rn(v.z, v.w);
}

// ---------------------------------------------------------------- Kernel A: Z[t][b][h] = b[h] + sum_f x[b][f][t] * Wx[f][h]  (HMMA fp16)
__global__ void __launch_bounds__(256, 2) zmat_kernel(const float* __restrict__ bias) {
    extern __shared__ __half hsm[];
    __half* As = hsm;                 // [2][32][136]
    __half* Bs = hsm + 2 * 32 * 136;  // [2][32][136]
    int h0 = blockIdx.x * 128;
    int t0 = blockIdx.y * 128;
    int b  = blockIdx.z;
    int tid = threadIdx.x;
    int w = tid >> 5, lane = tid & 31;

    float d[8][2][4];
    #pragma unroll
    for (int mt = 0; mt < 8; mt++)
        #pragma unroll
        for (int nt = 0; nt < 2; nt++)
            #pragma unroll
            for (int j = 0; j < 4; j++) d[mt][nt][j] = 0.f;

    auto issue = [&](int ci, int buf) {
        int f0 = ci * 32;
        __half* Ad = As + buf * 4352;
        __half* Bd = Bs + buf * 4352;
        #pragma unroll
        for (int it = 0; it < 2; it++) {
            int idx = it * 256 + tid;
            int f = idx >> 4, sg = idx & 15;
            cp_async16(Ad + f * 136 + sg * 8, g_xh + ((size_t)b * FF + f0 + f) * TT + t0 + sg * 8);
            cp_async16(Bd + f * 136 + sg * 8, g_Wxh + (size_t)(f0 + f) * HH + h0 + sg * 8);
        }
        cp_commit();
    };

    int brow = ((lane >> 3) & 1) * 8 + (lane & 7);
    int arow = ((lane >> 4) & 1) * 8 + (lane & 7);
    int acol = ((lane >> 3) & 1) * 8;

    issue(0, 0);
    for (int ci = 0; ci < 8; ci++) {
        if (ci < 7) { issue(ci + 1, (ci + 1) & 1); cp_wait<1>(); }
        else cp_wait<0>();
        __syncthreads();
        uint32_t a_base = (uint32_t)__cvta_generic_to_shared(As + (ci & 1) * 4352);
        uint32_t b_base = (uint32_t)__cvta_generic_to_shared(Bs + (ci & 1) * 4352);
        #pragma unroll
        for (int kt = 0; kt < 2; kt++) {
            uint32_t Bf[2][2];
            #pragma unroll
            for (int nt = 0; nt < 2; nt++) {
                uint32_t baddr = b_base + (uint32_t)((kt * 16 + brow) * 136 + w * 16 + nt * 8) * 2;
                ldsm_x2_trans(Bf[nt][0], Bf[nt][1], baddr);
            }
            #pragma unroll
            for (int mt = 0; mt < 8; mt++) {
                uint32_t a0, a1, a2, a3;
                uint32_t aaddr = a_base + (uint32_t)((kt * 16 + arow) * 136 + mt * 16 + acol) * 2;
                ldsm_x4_trans(a0, a1, a2, a3, aaddr);
                mma16816(d[mt][0][0], d[mt][0][1], d[mt][0][2], d[mt][0][3],
                         a0, a1, a2, a3, Bf[0][0], Bf[0][1]);
                mma16816(d[mt][1][0], d[mt][1][1], d[mt][1][2], d[mt][1][3],
                         a0, a1, a2, a3, Bf[1][0], Bf[1][1]);
            }
        }
        __syncthreads();
    }

    int nc = (lane & 3) * 2;
    int mrow = lane >> 2;
    #pragma unroll
    for (int nt = 0; nt < 2; nt++) {
        int col = h0 + w * 16 + nt * 8 + nc;
        float2 bv = *reinterpret_cast<const float2*>(bias + col);
        #pragma unroll
        for (int mt = 0; mt < 8; mt++) {
            int ta = t0 + mt * 16 + mrow;
            int tb = ta + 8;
            *reinterpret_cast<float2*>(g_Z + ((size_t)ta * BB + b) * HH + col) =
                make_float2(d[mt][nt][0] + bv.x, d[mt][nt][1] + bv.y);
            *reinterpret_cast<float2*>(g_Z + ((size_t)tb * BB + b) * HH + col) =
                make_float2(d[mt][nt][2] + bv.x, d[mt][nt][3] + bv.y);
        }
    }
}

// ---------------------------------------------------------------- Kernel B: persistent recurrence — self-staging HMMA dataflow (R15 config)
// 128 CTAs: (r: 16 batch rows) x (c: 32 H cols). 256 threads, 8 compute warps.
// Warp w owns k in [128w, 128w+128): lanes 0-3 poll its 4 producer flags, lane 0 issues
// its own 4KB TMA into warp-private SMEM, private mbarrier, then ldsm+mma.
__global__ void __launch_bounds__(256, 1) rnn_rec_kernel(const float* __restrict__ Wh) {
    extern __shared__ float smem[];
    // [0..16 floats): 8 mbarriers (one per warp)
    __half* wh_h = reinterpret_cast<__half*>(smem + 16);        // [1024][32] halfs (64KB), init-only
    __half* st_h = reinterpret_cast<__half*>(smem + 16 + 16384);// [1024][16] halfs (32KB)
    float*  red_s = smem + 16 + 16384 + 8192;                   // [8][512] floats (16KB)
    float*  fin   = red_s + 4096;                               // [16][33] floats
    uint32_t mbar0 = (uint32_t)__cvta_generic_to_shared(smem);
    uint32_t st_base = (uint32_t)__cvta_generic_to_shared(st_h);
    uint32_t wh_base = (uint32_t)__cvta_generic_to_shared(wh_h);

    int tid  = threadIdx.x;
    int wid  = tid >> 5, lane = tid & 31;
    int c = blockIdx.x & 31;                // column tile (32 cols)
    int r = blockIdx.x >> 5;                // batch row group (16 rows)
    int r16 = r * 16;

    if (tid == 0) {
        #pragma unroll
        for (int w2 = 0; w2 < 8; w2++) mbar_init(mbar0 + w2 * 8, 1);
    }
    // Wh tile -> fp16 SMEM [k][32]
    for (int i = tid; i < 32768; i += 256) {
        int k = i >> 5, n = i & 31;
        wh_h[i] = __float2half_rn(Wh[k * HH + c * 32 + n]);
    }
    __syncthreads();

    unsigned* myflag = &g_flag[(r * 32 + c) * 32];

    int w = wid;
    uint32_t mymb = mbar0 + w * 8;

    // Preload B fragments (Wh^T tiles) into registers: 8 k-tiles x 4 n-tiles x 2 regs.
    uint32_t Bf[8][4][2];
    {
        int brow = ((lane >> 3) & 1) * 8 + (lane & 7);
        #pragma unroll
        for (int kt = 0; kt < 8; kt++) {
            int krow = w * 128 + kt * 16 + brow;
            #pragma unroll
            for (int nt = 0; nt < 4; nt++) {
                uint32_t addr = wh_base + (uint32_t)(krow * 32 + nt * 8) * 2;
                ldsm_x2_trans(Bf[kt][nt][0], Bf[kt][nt][1], addr);
            }
        }
    }

    // A ldmatrix (x4.trans from [k][16b]) address pattern
    int arow = ((lane >> 4) & 1) * 8 + (lane & 7);
    int acol = ((lane >> 3) & 1) * 8;

    // producer flags for lanes 0-3: CTAs c' = w*4 + lane cover h in [c'*32, c'*32+32)
    const unsigned* pf = &g_flag[(r * 32 + w * 4 + (lane & 3)) * 32];

    // epilogue mapping: 2 outputs per thread
    int o  = tid * 2;
    int em = o >> 5, en = o & 31;
    int brow2 = r16 + em, hcol = c * 32 + en;
    int j2 = tid * 2;
    int hl = j2 >> 4, em2 = j2 & 15;

    // D-frag store mapping
    int m0 = lane >> 2;
    int nc = (lane & 3) * 2;

    float* zbase = g_Z + (size_t)brow2 * HH + hcol;

    for (int t = 0; t < TT; ++t) {
        float2 zq = *reinterpret_cast<const float2*>(zbase + (size_t)t * (BB * HH));

        float d[4][4];
        #pragma unroll
        for (int nt = 0; nt < 4; nt++)
            #pragma unroll
            for (int j = 0; j < 4; j++) d[nt][j] = 0.f;

        if (t > 0) {
            // self-stage: poll own 4 producers, then TMA own 128k x 16b slice (4KB)
            if (lane < 4) {
                while (ld_acq_gpu(pf) < (unsigned)t) { }
            }
            __syncwarp();
            if (lane == 0) {
                asm volatile("fence.proxy.async;" ::: "memory");
                const __half* src = g_ST2h[(t + 1) & 1][r] + w * 2048;   // 2048 halfs = 4KB
                mbar_expect_tx(mymb, 4096u);
                uint32_t dst = (uint32_t)__cvta_generic_to_shared(st_h + w * 2048);
                bulk_g2s(dst, src, 4096u, mymb);
            }
            mbar_wait(mymb, (t - 1) & 1);
            #pragma unroll
            for (int kt = 0; kt < 8; kt++) {
                uint32_t a0, a1, a2, a3;
                uint32_t addr = st_base + (uint32_t)((w * 128 + kt * 16 + arow) * 16 + acol) * 2;
                ldsm_x4_trans(a0, a1, a2, a3, addr);
                #pragma unroll
                for (int nt = 0; nt < 4; nt++)
                    mma16816(d[nt][0], d[nt][1], d[nt][2], d[nt][3],
                             a0, a1, a2, a3, Bf[kt][nt][0], Bf[kt][nt][1]);
            }
        }

        // partials: red_s[w][m*32 + n]
        {
            float* rp = red_s + w * 512;
            #pragma unroll
            for (int nt = 0; nt < 4; nt++) {
                *reinterpret_cast<float2*>(rp + m0 * 32 + nt * 8 + nc)       = make_float2(d[nt][0], d[nt][1]);
                *reinterpret_cast<float2*>(rp + (m0 + 8) * 32 + nt * 8 + nc) = make_float2(d[nt][2], d[nt][3]);
            }
        }
        bar_named(1, 256);
        float s0, s1;
        {
            float2 v = make_float2(0.f, 0.f);
            #pragma unroll
            for (int ww = 0; ww < 8; ww++) {
                float2 p = *reinterpret_cast<const float2*>(red_s + ww * 512 + o);
                v.x += p.x; v.y += p.y;
            }
            s0 = tanhf(zq.x + v.x);
            s1 = tanhf(zq.y + v.y);
            fin[em * 33 + en]     = s0;
            fin[em * 33 + en + 1] = s1;
        }
        bar_named(1, 256);
        {
            // coalesced transposed fp16 state store
            float a  = fin[em2 * 33 + hl];
            float b2 = fin[(em2 + 1) * 33 + hl];
            __half2* stp = reinterpret_cast<__half2*>(g_ST2h[t & 1][r] + (size_t)(c * 32 + hl) * 16 + em2);
            *stp = __floats2half2_rn(a, b2);
        }
        bar_named(1, 256);    // all state stores ordered before release
        if (tid == 0) {
            asm volatile("fence.acq_rel.gpu;" ::: "memory");
            unsigned g = (unsigned)(t + 1);
            asm volatile("st.relaxed.gpu.global.u32 [%0], %1;" :: "l"(myflag), "r"(g) : "memory");
        }
        // fp16 row-major states for out_kernel (off inter-CTA critical path)
        __half2* shp = reinterpret_cast<__half2*>(g_Sh + ((size_t)t * BB + brow2) * HH + hcol);
        *shp = __floats2half2_rn(s0, s1);
    }
}

// ---------------------------------------------------------------- Kernel C: out = S(fp16) @ Wout(fp16) + bout, HMMA (2 CTAs/SM)
__global__ void __launch_bounds__(256, 2) out_kernel(const float* __restrict__ bout,
                                                     float* __restrict__ out) {
    extern __shared__ __half hsm[];
    __half* As = hsm;                 // [2][128][40]
    __half* Bs = hsm + 2 * 128 * 40;  // [2][32][136]
    int o0 = blockIdx.x * 128;
    int r0 = blockIdx.y * 128;
    int tid = threadIdx.x;
    int w = tid >> 5, lane = tid & 31;

    float d[8][2][4];
    #pragma unroll
    for (int mt = 0; mt < 8; mt++)
        #pragma unroll
        for (int nt = 0; nt < 2; nt++)
            #pragma unroll
            for (int j = 0; j < 4; j++) d[mt][nt][j] = 0.f;

    auto issue = [&](int ci, int buf) {
        int f0 = ci * 32;
        __half* Ad = As + buf * 5120;
        __half* Bd = Bs + buf * 4352;
        #pragma unroll
        for (int it = 0; it < 2; it++) {
            int idx = it * 256 + tid;
            int row = idx >> 2, seg = idx & 3;
            cp_async16(Ad + row * 40 + seg * 8, g_Sh + (size_t)(r0 + row) * HH + f0 + seg * 8);
            int kr = idx >> 4, sg = idx & 15;
            cp_async16(Bd + kr * 136 + sg * 8, g_Wouth + (size_t)(f0 + kr) * OO + o0 + sg * 8);
        }
        cp_commit();
    };

    int brow = ((lane >> 3) & 1) * 8 + (lane & 7);
    int amr = lane & 15;
    int akc = (lane >> 4) * 8;

    issue(0, 0);
    for (int ci = 0; ci < 32; ci++) {
        if (ci < 31) { issue(ci + 1, (ci + 1) & 1); cp_wait<1>(); }
        else cp_wait<0>();
        __syncthreads();
        const __half* Ac = As + (ci & 1) * 5120;
        const __half* Bc = Bs + (ci & 1) * 4352;
        uint32_t a_base = (uint32_t)__cvta_generic_to_shared(Ac);
        uint32_t b_base = (uint32_t)__cvta_generic_to_shared(Bc);
        #pragma unroll
        for (int kt = 0; kt < 2; kt++) {
            uint32_t Bf[2][2];
            #pragma unroll
            for (int nt = 0; nt < 2; nt++) {
                uint32_t baddr = b_base + (uint32_t)((kt * 16 + brow) * 136 + w * 16 + nt * 8) * 2;
                ldsm_x2_trans(Bf[nt][0], Bf[nt][1], baddr);
            }
            #pragma unroll
            for (int mt = 0; mt < 8; mt++) {
                uint32_t a0, a1, a2, a3;
                uint32_t aaddr = a_base + (uint32_t)((mt * 16 + amr) * 40 + kt * 16 + akc) * 2;
                ldsm_x4(a0, a1, a2, a3, aaddr);
                mma16816(d[mt][0][0], d[mt][0][1], d[mt][0][2], d[mt][0][3],
                         a0, a1, a2, a3, Bf[0][0], Bf[0][1]);
                mma16816(d[mt][1][0], d[mt][1][1], d[mt][1][2], d[mt][1][3],
                         a0, a1, a2, a3, Bf[1][0], Bf[1][1]);
            }
        }
        __syncthreads();
    }

    int nc = (lane & 3) * 2;
    int mrow = lane >> 2;
    #pragma unroll
    for (int nt = 0; nt < 2; nt++) {
        int col = o0 + w * 16 + nt * 8 + nc;
        float2 bv = *reinterpret_cast<const float2*>(bout + col);
        #pragma unroll
        for (int mt = 0; mt < 8; mt++) {
            int g0 = r0 + mt * 16 + mrow;
            int g1 = g0 + 8;
            int t0r = g0 >> 6, b0r = g0 & 63;
            int t1r = g1 >> 6, b1r = g1 & 63;
            *reinterpret_cast<float2*>(out + (size_t)b0r * (TT * OO) + t0r * OO + col) =
                make_float2(d[mt][nt][0] + bv.x, d[mt][nt][1] + bv.y);
            *reinterpret_cast<float2*>(out + (size_t)b1r * (TT * OO) + t1r * OO + col) =
                make_float2(d[mt][nt][2] + bv.x, d[mt][nt][3] + bv.y);
        }
    }
}

// ---------------------------------------------------------------- launch
extern "C" void kernel_launch(void* const* d_in, const int* in_sizes, int n_in,
                              void* d_out, int out_size) {
    const float* x    = (const float*)d_in[0];   // (B,F,T)
    const float* Wx   = (const float*)d_in[1];   // (F,H)
    const float* Wh   = (const float*)d_in[2];   // (H,H)
    const float* bv   = (const float*)d_in[3];   // (H,)
    const float* Wout = (const float*)d_in[4];   // (H,O)
    const float* bo   = (const float*)d_in[5];   // (O,)
    float* out = (float*)d_out;                  // (B,T,O)

    (void)in_sizes; (void)n_in; (void)out_size;

    // Phase 0: reset flags + fp16 conversions (x, Wx, Wout)
    reset_kernel<<<1, 256>>>();
    wcvt_kernel<<<(HH * OO) / 256, 256>>>(Wout);
    wxcvt_kernel<<<(FF * HH) / 256, 256>>>(Wx);
    xcvt_kernel<<<(int)(((size_t)BB * FF * TT) / 1024), 256>>>(x);

    // Phase 1: Z = x@Wx + b (HMMA fp16, 128x128 tiles, 2 CTAs/SM)
    size_t zsm = (size_t)(2 * 32 * 136 * 2) * sizeof(__half);   // 34816 B
    cudaFuncSetAttribute(zmat_kernel, cudaFuncAttributeMaxDynamicSharedMemorySize, (int)zsm);
    dim3 ga(HH / 128, TT / 128, BB);
    zmat_kernel<<<ga, 256, zsm>>>(bv);

    // Phase 2: persistent recurrence (self-staging HMMA dataflow, 256 threads)
    size_t dyn = (size_t)(16 + 16384 + 8192 + 4096 + 528) * sizeof(float);  // 116864 B
    cudaFuncSetAttribute(rnn_rec_kernel, cudaFuncAttributeMaxDynamicSharedMemorySize, 232448);
    rnn_rec_kernel<<<NB, 256, dyn>>>(Wh);

    // Phase 3: output projection (HMMA fp16, 128x128 tiles, 2 CTAs/SM)
    size_t osm = (2 * 128 * 40 + 2 * 32 * 136) * sizeof(__half);  // 37888 B
    cudaFuncSetAttribute(out_kernel, cudaFuncAttributeMaxDynamicSharedMemorySize, (int)osm);
    dim3 gc(OO / 128, (TT * BB) / 128);   // n-inner for A-tile L2 reuse
    out_kernel<<<gc, 256, osm>>>(bo, out);
}